// round 10
// baseline (speedup 1.0000x reference)
#include <cuda_runtime.h>
#include <math.h>

#define NBOX   4096
#define NFRAME 4
#define CAP    64          // global overflow region per box (out-edges beyond OCAP)
#define OCAP   12          // inline out-edges in shared
#define HCAP   64          // max collected out-edges per box
#define MAXC   16
#define BIGTH  32
#define NCELL  256
#define IOU_T   0.3f
#define SCORE_T 0.2f
#define SKW(i) ((i) + ((i) >> 5))
#define XLO    (-120.0f)
#define INVW   (256.0f/240.0f)

// ---------------- global scratch ----------------
__device__ float d_sbox  [NFRAME*NBOX*7];
__device__ float d_sscore[NFRAME*NBOX];
__device__ float d_slabel[NFRAME*NBOX];
__device__ int   d_nbr   [NFRAME*NBOX*CAP];     // out-edge overflow
__device__ int   d_clusIdx[NFRAME*NBOX*MAXC];
__device__ int   d_count [NFRAME*NBOX];
__device__ int   d_lead  [NFRAME*NBOX];

// ---------------- shared memory layout (bytes) ----------------
// region A (0..67584): radix sort buffers  ->  cellGeo float4[3328] (53248)
//                       ->  parent u32[4096] @0 | cnt u32[4096] @16384 | start u32[4096] @32768
// region B (67584..80896): cellArea f32[3328]  ->  sMem u16[4096] (8192)
// region C (80896..87552): cellGidx u16[3328]
// region D (87552..185856): outl u16[4096*12]
// E: hist u32[768] @185856 | cstart u32[768] @188928 | cursor u32[768] @192000
// F: odeg u8[4096] @195072 | alive u8[4096] @199168
#define OFF_AREA   67584
#define OFF_SMEMB  67584
#define OFF_GIDX   80896
#define OFF_OUTL   87552
#define OFF_HIST   185856
#define OFF_CSTART 188928
#define OFF_CURSOR 192000
#define OFF_ODEG   195072
#define OFF_ALIVE  199168
#define SMEM_MEGA  203264

__device__ __forceinline__ int uf_find(unsigned* par, int x)
{
    int p = (int)par[x];
    while (p != x) {
        int gp = (int)par[p];
        par[x] = (unsigned)gp;
        x = gp; p = (int)par[x];
    }
    return x;
}

__device__ __forceinline__ void uf_union(unsigned* par, int a, int b)
{
    for (;;) {
        a = uf_find(par, a); b = uf_find(par, b);
        if (a == b) return;
        int hi = a > b ? a : b, lo = a > b ? b : a;
        if (atomicCAS(&par[hi], (unsigned)hi, (unsigned)lo) == (unsigned)hi) return;
        a = hi; b = lo;
    }
}

__global__ void __launch_bounds__(1024) k_mega(const float* __restrict__ boxes,
                                               const float* __restrict__ scores,
                                               const int*   __restrict__ labels)
{
    extern __shared__ char smc[];
    unsigned* sortb = (unsigned*)smc;                              // 4 x 4224 u32
    float4*   cellGeo  = (float4*)smc;
    float*    cellArea = (float*)(smc + OFF_AREA);
    unsigned short* cellGidx = (unsigned short*)(smc + OFF_GIDX);
    unsigned short* outl     = (unsigned short*)(smc + OFF_OUTL);
    unsigned* hist   = (unsigned*)(smc + OFF_HIST);
    unsigned* cstart = (unsigned*)(smc + OFF_CSTART);
    unsigned* cursor = (unsigned*)(smc + OFF_CURSOR);
    unsigned char* odeg  = (unsigned char*)(smc + OFF_ODEG);
    unsigned char* alive = (unsigned char*)(smc + OFF_ALIVE);
    unsigned* parent = (unsigned*)smc;                             // overlays cellGeo later
    unsigned* cnt    = (unsigned*)(smc + 16384);
    unsigned* start  = (unsigned*)(smc + 32768);
    unsigned short* sMem = (unsigned short*)(smc + OFF_SMEMB);

    __shared__ unsigned wsA[32], wsB[32];
    __shared__ unsigned wps[24];
    __shared__ int vcount, nbig;
    __shared__ int bigroots[64];

    int f = blockIdx.x, tid = threadIdx.x, lane = tid & 31, wid = tid >> 5;
    int base = f*NBOX;
    const float* sc = scores + f*NBOX;

    // ---- phase 0: keys + valid count ----
    if (tid == 0) { vcount = 0; nbig = 0; }
    if (tid < 768) hist[tid] = 0;
    int vloc = 0;
    for (int i = tid; i < NBOX; i += 1024) {
        float s = sc[i];
        bool v = (s > SCORE_T);
        float skey = v ? s : -INFINITY;
        unsigned u = __float_as_uint(skey);
        u = (u & 0x80000000u) ? ~u : (u | 0x80000000u);
        sortb[SKW(i)] = ~u;                       // key buf 0
        sortb[2*4224 + SKW(i)] = (unsigned)i;     // payload buf 0
        d_lead[base + i] = 0;
        vloc += v ? 1 : 0;
    }
    #pragma unroll
    for (int o = 16; o; o >>= 1) vloc += __shfl_xor_sync(0xffffffffu, vloc, o);
    if (lane == 0 && vloc) atomicAdd(&vcount, vloc);
    __syncthreads();

    // ---- phase 1: 16-pass 2-bit LSD radix (stable) ----
    int cur = 0;
    for (int pass = 0; pass < 16; ++pass) {
        int sh = pass * 2;
        unsigned* kc = sortb + cur*4224;          unsigned* pc = sortb + 2*4224 + cur*4224;
        unsigned* kn = sortb + (cur^1)*4224;      unsigned* pn = sortb + 2*4224 + (cur^1)*4224;
        int b0 = tid*4;
        unsigned k0=kc[SKW(b0)],k1=kc[SKW(b0+1)],k2=kc[SKW(b0+2)],k3=kc[SKW(b0+3)];
        unsigned q0=pc[SKW(b0)],q1=pc[SKW(b0+1)],q2=pc[SKW(b0+2)],q3=pc[SKW(b0+3)];
        int d0=(k0>>sh)&3, d1=(k1>>sh)&3, d2=(k2>>sh)&3, d3=(k3>>sh)&3;
        unsigned cA=0, cB=0;
        #define ADDC(d) { if((d)==0) cA+=1u; else if((d)==1) cA+=(1u<<16); \
                          else if((d)==2) cB+=1u; else cB+=(1u<<16); }
        ADDC(d0) ADDC(d1) ADDC(d2) ADDC(d3)
        unsigned a=cA, b=cB;
        #pragma unroll
        for (int o=1;o<32;o<<=1){
            unsigned ta=__shfl_up_sync(0xffffffffu,a,o);
            unsigned tb=__shfl_up_sync(0xffffffffu,b,o);
            if(lane>=o){a+=ta;b+=tb;}
        }
        if (lane==31){ wsA[wid]=a; wsB[wid]=b; }
        __syncthreads();
        if (wid==0){
            unsigned x=wsA[lane], y=wsB[lane];
            #pragma unroll
            for(int o=1;o<32;o<<=1){
                unsigned tx=__shfl_up_sync(0xffffffffu,x,o);
                unsigned ty=__shfl_up_sync(0xffffffffu,y,o);
                if(lane>=o){x+=tx;y+=ty;}
            }
            wsA[lane]=x; wsB[lane]=y;
        }
        __syncthreads();
        unsigned wa = wid ? wsA[wid-1] : 0u, wb = wid ? wsB[wid-1] : 0u;
        unsigned exA = a - cA + wa, exB = b - cB + wb;
        unsigned totA = wsA[31], totB = wsB[31];
        unsigned T0 = totA & 0xffffu, T1 = totA >> 16, T2 = totB & 0xffffu;
        unsigned bs1 = T0, bs2 = T0+T1, bs3 = bs2+T2;
        unsigned off[4];
        off[0]=(exA&0xffffu); off[1]=bs1+(exA>>16);
        off[2]=bs2+(exB&0xffffu); off[3]=bs3+(exB>>16);
        unsigned dd;
        dd=off[d0]++; kn[SKW(dd)]=k0; pn[SKW(dd)]=q0;
        dd=off[d1]++; kn[SKW(dd)]=k1; pn[SKW(dd)]=q1;
        dd=off[d2]++; kn[SKW(dd)]=k2; pn[SKW(dd)]=q2;
        dd=off[d3]++; kn[SKW(dd)]=k3; pn[SKW(dd)]=q3;
        __syncthreads();
        cur ^= 1;
    }
    int V = vcount;

    // ---- phase 2: gather + geometry (registers) + cell histogram ----
    unsigned* pf = sortb + 2*4224 + cur*4224;
    int  r0 = tid*4;
    float X1[4],X2[4],Y1[4],Y2[4],AR[4],XL1[4],XL2[4];
    int  LB[4]; bool VA[4];
    #pragma unroll
    for (int u = 0; u < 4; ++u) {
        int r = r0 + u;
        int o = (int)pf[SKW(r)];
        const float* bx = boxes + ((size_t)f*NBOX + o)*7;
        float b0 = bx[0], b1 = bx[1], b2 = bx[2], b3 = bx[3],
              b4 = bx[4], b5 = bx[5], b6 = bx[6];
        float s  = sc[o];
        int  lab = labels[f*NBOX + o];
        float off = (float)lab * 10000.0f;
        float cx = b0 + off, cy = b1;
        float hx = b3 * 0.5f, hy = b4 * 0.5f;
        float x1 = cx - hx, x2 = cx + hx, y1 = cy - hy, y2 = cy + hy;
        float area = (x2 - x1) * (y2 - y1);       // exact ref op order
        int idx = base + r;
        float* sb = d_sbox + (size_t)idx*7;
        sb[0]=b0; sb[1]=b1; sb[2]=b2; sb[3]=b3; sb[4]=b4; sb[5]=b5; sb[6]=b6;
        d_sscore[idx] = s; d_slabel[idx] = (float)lab;
        X1[u]=x1; X2[u]=x2; Y1[u]=y1; Y2[u]=y2; AR[u]=area;
        XL1[u]=x1-off; XL2[u]=x2-off; LB[u]=lab;
        VA[u] = (r < V);
        if (VA[u]) {
            int cell = (int)((XL1[u] - XLO) * INVW);
            cell = cell < 0 ? 0 : (cell > 255 ? 255 : cell);
            atomicAdd(&hist[lab*NCELL + cell], 1u);
        }
    }
    __syncthreads();   // pf dead; hist complete

    // ---- phase 2b: 768-cell exclusive prefix ----
    {
        unsigned pv = 0, pincl = 0;
        if (tid < 768) {
            pv = hist[tid];
            unsigned x = pv;
            #pragma unroll
            for (int o=1;o<32;o<<=1){ unsigned t=__shfl_up_sync(0xffffffffu,x,o); if(lane>=o) x+=t; }
            if (lane == 31) wps[tid>>5] = x;
            pincl = x;
        }
        __syncthreads();
        if (tid == 0) {
            unsigned acc = 0;
            for (int k = 0; k < 24; ++k) { unsigned t = wps[k]; wps[k] = acc; acc += t; }
        }
        __syncthreads();
        if (tid < 768) {
            unsigned st = wps[tid>>5] + pincl - pv;
            cstart[tid] = st; cursor[tid] = st;
        }
    }
    __syncthreads();

    // ---- phase 2c: scatter geometry into cell-ordered shared arrays ----
    #pragma unroll
    for (int u = 0; u < 4; ++u) {
        if (VA[u]) {
            int cell = (int)((XL1[u] - XLO) * INVW);
            cell = cell < 0 ? 0 : (cell > 255 ? 255 : cell);
            unsigned pos = atomicAdd(&cursor[LB[u]*NCELL + cell], 1u);
            cellGeo [pos] = make_float4(X1[u], X2[u], Y1[u], Y2[u]);
            cellArea[pos] = AR[u];
            cellGidx[pos] = (unsigned short)(r0 + u);
        }
    }
    __syncthreads();

    // ---- phase 3: windowed out-edge lists (ascending) ----
    {
        int hits[HCAP];
        for (int u = 0; u < 4; ++u) {
            int r = r0 + u;
            int hc = 0;
            if (VA[u]) {
                int clo = (int)((XL1[u] - 4.6f - XLO) * INVW);
                int chi = (int)((XL2[u] + 0.1f - XLO) * INVW);
                clo = clo < 0 ? 0 : (clo > 255 ? 255 : clo);
                chi = chi < 0 ? 0 : (chi > 255 ? 255 : chi);
                int hbase = LB[u]*NCELL;
                float x1=X1[u], x2=X2[u], y1=Y1[u], y2=Y2[u], ar=AR[u];
                for (int cell = clo; cell <= chi; ++cell) {
                    int s = (int)cstart[hbase + cell];
                    int n = (int)hist  [hbase + cell];
                    for (int k = s; k < s + n; ++k) {
                        float4 t = cellGeo[k];
                        float ix = fminf(x2, t.y) - fmaxf(x1, t.x);
                        float iy = fminf(y2, t.w) - fmaxf(y1, t.z);
                        if (ix > 0.f && iy > 0.f) {
                            float inter = ix * iy;
                            float den = fmaxf(ar + cellArea[k] - inter, 1e-6f);
                            if (inter / den > IOU_T) {
                                int j = cellGidx[k];
                                if (j > r && hc < HCAP) hits[hc++] = j;
                            }
                        }
                    }
                }
                // sort ascending
                for (int a = 1; a < hc; ++a) {
                    int v = hits[a], b = a - 1;
                    while (b >= 0 && hits[b] > v) { hits[b+1] = hits[b]; --b; }
                    hits[b+1] = v;
                }
                int m = hc < OCAP ? hc : OCAP;
                for (int k = 0; k < m; ++k) outl[r*OCAP + k] = (unsigned short)hits[k];
                for (int k = OCAP; k < hc; ++k) d_nbr[(size_t)(base + r)*CAP + k - OCAP] = hits[k];
            }
            odeg[r]  = (unsigned char)hc;
            alive[r] = VA[u] ? 1 : 0;
        }
    }
    __syncthreads();   // cellGeo/cellArea dead

    // ---- phase 4: union-find over out-edges ----
    for (int i = tid; i < NBOX; i += 1024) { parent[i] = (unsigned)i; cnt[i] = 0; }
    __syncthreads();
    for (int i = tid; i < V; i += 1024) {
        int od = odeg[i];
        for (int k = 0; k < od; ++k) {
            int j = (k < OCAP) ? (int)outl[i*OCAP + k]
                               : d_nbr[(size_t)(base + i)*CAP + k - OCAP];
            uf_union(parent, i, j);
        }
    }
    __syncthreads();
    for (int i = tid; i < NBOX; i += 1024) {
        int r = i;
        while ((int)parent[r] != r) r = (int)parent[r];
        parent[i] = (unsigned)r;
    }
    __syncthreads();

    // ---- phase 5: component grouping ----
    for (int i = tid; i < V; i += 1024) atomicAdd(&cnt[parent[i]], 1u);
    __syncthreads();
    {
        int i0 = tid * 4;
        unsigned c0 = cnt[i0], c1 = cnt[i0+1], c2 = cnt[i0+2], c3 = cnt[i0+3];
        unsigned s = c0 + c1 + c2 + c3;
        unsigned x = s;
        #pragma unroll
        for (int o = 1; o < 32; o <<= 1) { unsigned t = __shfl_up_sync(0xffffffffu, x, o); if (lane >= o) x += t; }
        if (lane == 31) wsA[wid] = x;
        __syncthreads();
        if (wid == 0) {
            unsigned v = wsA[lane];
            #pragma unroll
            for (int o = 1; o < 32; o <<= 1) { unsigned t = __shfl_up_sync(0xffffffffu, v, o); if (lane >= o) v += t; }
            wsA[lane] = v;
        }
        __syncthreads();
        unsigned excl = x - s + (wid ? wsA[wid-1] : 0u);
        start[i0]   = excl;
        start[i0+1] = excl + c0;
        start[i0+2] = excl + c0 + c1;
        start[i0+3] = excl + c0 + c1 + c2;
    }
    __syncthreads();
    for (int i = tid; i < V; i += 1024) {
        int r = (int)parent[i];
        if (cnt[r] <= BIGTH) {
            unsigned p = atomicAdd(&start[r], 1u);
            sMem[p] = (unsigned short)i;
        }
        if (r == i && cnt[i] > BIGTH) {
            int p = atomicAdd(&nbig, 1);
            if (p < 64) bigroots[p] = i;
        }
    }
    __syncthreads();

    // ---- phase 6a: small comps, exact serial greedy per thread ----
    for (int rr = tid; rr < V; rr += 1024) {
        if ((int)parent[rr] != rr) continue;
        int cc = (int)cnt[rr];
        if (cc > BIGTH) continue;
        int beg = (int)start[rr] - cc;
        for (int a = 1; a < cc; ++a) {
            unsigned short v = sMem[beg + a];
            int b = a - 1;
            while (b >= 0 && sMem[beg + b] > v) { sMem[beg + b + 1] = sMem[beg + b]; --b; }
            sMem[beg + b + 1] = v;
        }
        for (int a = 0; a < cc; ++a) {
            int i = sMem[beg + a];
            if (!alive[i]) continue;
            alive[i] = 0;
            int od = odeg[i];
            int* outp = d_clusIdx + (base + i)*MAXC;
            outp[0] = i;
            int r = 1;
            for (int k = 0; k < od; ++k) {
                int j = (k < OCAP) ? (int)outl[i*OCAP + k]
                                   : d_nbr[(size_t)(base + i)*CAP + k - OCAP];
                if (alive[j]) { alive[j] = 0; if (r < MAXC) outp[r] = j; ++r; }
            }
            d_count[base + i] = (r < MAXC) ? r : MAXC;
            d_lead [base + i] = 1;
        }
    }

    // ---- phase 6b: big comps, one warp each (exact order) ----
    int nb = nbig > 64 ? 64 : nbig;
    for (int bi = wid; bi < nb; bi += 32) {
        int root = bigroots[bi];
        for (int b0 = root; b0 < V; b0 += 32) {
            int i = b0 + lane;
            bool mem = (i < V) && ((int)parent[i] == root) && alive[i];
            unsigned mask = __ballot_sync(0xffffffffu, mem);
            while (mask) {
                int src = __ffs((int)mask) - 1;
                int L = b0 + src;
                int od = odeg[L];
                int rb = 1;
                for (int c = 0; c < od; c += 32) {
                    int k = c + lane;
                    int j = -1;
                    if (k < od) j = (k < OCAP) ? (int)outl[L*OCAP + k]
                                               : d_nbr[(size_t)(base + L)*CAP + k - OCAP];
                    bool kill = (j >= 0) && alive[j];
                    unsigned km = __ballot_sync(0xffffffffu, kill);
                    if (kill) {
                        int r = rb + __popc(km & ((1u << lane) - 1u));
                        alive[j] = 0;
                        if (r < MAXC) d_clusIdx[(base + L)*MAXC + r] = j;
                    }
                    rb += __popc(km);
                }
                if (lane == src) {
                    alive[L] = 0;
                    d_clusIdx[(base + L)*MAXC] = L;
                    d_count[base + L] = (rb < MAXC) ? rb : MAXC;
                    d_lead [base + L] = 1;
                }
                __syncwarp();
                bool mem2 = (i < V) && (i > L) && ((int)parent[i] == root) && alive[i];
                mask = __ballot_sync(0xffffffffu, mem2);
            }
        }
    }
}

// ---------------- kernel 2: MLP + softmax merge + output --------------------
__global__ void __launch_bounds__(256) k_merge(const float* __restrict__ W1,
                                               const float* __restrict__ b1,
                                               const float* __restrict__ W2,
                                               const float* __restrict__ b2,
                                               float* __restrict__ out, int writeLead)
{
    __shared__ float sW1[448], sb1[64], sW2[64];
    __shared__ float sb2;
    int tid = threadIdx.x;
    int g = tid >> 4, l = tid & 15;
    unsigned gm = 0xFFFFu << (tid & 16);
    int row = blockIdx.x * 16 + g;
    int lead = d_lead[row];
    int cnt  = lead ? d_count[row] : 0;

    int need = __syncthreads_or(cnt >= 2);
    if (need) {
        for (int t = tid; t < 448; t += 256) sW1[t] = W1[t];
        if (tid < 64) { sb1[tid] = b1[tid]; sW2[tid] = W2[tid]; }
        if (tid == 0) sb2 = b2[0];
        __syncthreads();
    }

    float* infoOut = out + (size_t)row * 9;
    if (!lead) {
        if (l == 0) {
            #pragma unroll
            for (int d = 0; d < 9; ++d) infoOut[d] = 0.f;
            if (writeLead) out[(size_t)NFRAME*NBOX*9 + row] = 0.f;
        }
        return;
    }
    if (cnt == 1) {
        if (l == 0) {
            const float* own = d_sbox + (size_t)row * 7;
            infoOut[0]=own[0]; infoOut[1]=own[1]; infoOut[2]=own[2];
            infoOut[3]=own[3]; infoOut[4]=own[4]; infoOut[5]=own[5];
            infoOut[6]=own[6];
            infoOut[7]=d_sscore[row];
            infoOut[8]=d_slabel[row];
            if (writeLead) out[(size_t)NFRAME*NBOX*9 + row] = 1.f;
        }
        return;
    }
    bool ok = l < cnt;
    float c[7];
    int f = row >> 12;
    if (ok) {
        int nb = d_clusIdx[row*MAXC + l];
        const float* sp = d_sbox + ((size_t)(f*NBOX) + nb) * 7;
        #pragma unroll
        for (int d = 0; d < 7; ++d) c[d] = sp[d];
    } else {
        #pragma unroll
        for (int d = 0; d < 7; ++d) c[d] = 0.f;
    }
    float logit;
    if (ok) {
        float lg = 0.f;
        for (int k = 0; k < 64; ++k) {
            float h = sb1[k];
            #pragma unroll
            for (int d = 0; d < 7; ++d) h += c[d] * sW1[d*64 + k];
            h = fmaxf(h, 0.f);
            lg += h * sW2[k];
        }
        logit = lg + sb2;
    } else logit = -1e9f;

    float m = logit;
    #pragma unroll
    for (int o = 8; o; o >>= 1) m = fmaxf(m, __shfl_xor_sync(gm, m, o, 16));
    float p = ok ? expf(logit - m) : 0.f;
    float S = p;
    #pragma unroll
    for (int o = 8; o; o >>= 1) S += __shfl_xor_sync(gm, S, o, 16);
    float w = p / S;
    float mg[7];
    #pragma unroll
    for (int d = 0; d < 7; ++d) {
        float v = w * c[d];
        #pragma unroll
        for (int o = 8; o; o >>= 1) v += __shfl_xor_sync(gm, v, o, 16);
        mg[d] = v;
    }
    if (l == 0) {
        const float* own = d_sbox + (size_t)row * 7;
        infoOut[0] = mg[0]; infoOut[1] = mg[1]; infoOut[2] = mg[2];
        infoOut[3] = (mg[3] <= 0.f) ? own[3] : mg[3];
        infoOut[4] = (mg[4] <= 0.f) ? own[4] : mg[4];
        infoOut[5] = (mg[5] <= 0.f) ? own[5] : mg[5];
        infoOut[6] = mg[6];
        infoOut[7] = d_sscore[row];
        infoOut[8] = d_slabel[row];
        if (writeLead) out[(size_t)NFRAME*NBOX*9 + row] = 1.f;
    }
}

// ---------------- launch -----------------------------------------------------
extern "C" void kernel_launch(void* const* d_in, const int* in_sizes, int n_in,
                              void* d_out, int out_size)
{
    const float* boxes  = (const float*)d_in[0];
    const float* scores = (const float*)d_in[1];
    const int*   labels = (const int*)  d_in[2];
    const float* W1     = (const float*)d_in[3];
    const float* b1     = (const float*)d_in[4];
    const float* W2     = (const float*)d_in[5];
    const float* b2     = (const float*)d_in[6];
    float* out = (float*)d_out;

    int writeLead = (out_size >= NFRAME*NBOX*10) ? 1 : 0;

    static int inited = 0;
    if (!inited) {
        cudaFuncSetAttribute(k_mega, cudaFuncAttributeMaxDynamicSharedMemorySize, SMEM_MEGA);
        inited = 1;
    }

    k_mega<<<NFRAME, 1024, SMEM_MEGA>>>(boxes, scores, labels);
    k_merge<<<(NFRAME*NBOX)/16, 256>>>(W1, b1, W2, b2, out, writeLead);
}

// round 12
// speedup vs baseline: 1.3618x; 1.3618x over previous
#include <cuda_runtime.h>
#include <math.h>

#define NBOX   4096
#define NFRAME 4
#define CAP    128
#define MAXC   16
#define INL    8
#define IOU_T   0.3f
#define SCORE_T 0.2f
#define SKW(i) ((i) + ((i) >> 5))

// ---------------- scratch (static __device__, no allocations) ----------------
__device__ float d_sbox  [NFRAME*NBOX*7];
__device__ float d_sscore[NFRAME*NBOX];
__device__ float d_slabel[NFRAME*NBOX];
__device__ float d_x1[NFRAME*NBOX], d_x2[NFRAME*NBOX];
__device__ float d_y1[NFRAME*NBOX], d_y2[NFRAME*NBOX];
__device__ float d_areaA[NFRAME*NBOX];
__device__ int   d_V[NFRAME];
__device__ int   d_Vc[NFRAME*3];
__device__ float4 d_clsGeo [NFRAME*3*NBOX];
__device__ float  d_clsArea[NFRAME*3*NBOX];
__device__ int    d_clsG   [NFRAME*3*NBOX];
__device__ int   d_nbr[NFRAME*NBOX*CAP];
__device__ int   d_deg[NFRAME*NBOX];
__device__ int   d_selfpos[NFRAME*NBOX];
__device__ int   d_clusIdx[NFRAME*NBOX*MAXC];
__device__ int   d_count[NFRAME*NBOX];
__device__ int   d_lead[NFRAME*NBOX];

// ---------------- kernel 1: stable radix sort + gather + class partition ----
__global__ void __launch_bounds__(1024) k_sort(const float* __restrict__ boxes,
                                               const float* __restrict__ scores,
                                               const int*   __restrict__ labels)
{
    extern __shared__ unsigned sm[];
    unsigned* kb = sm;                 // [2][4224] keys (skewed)
    unsigned* pb = sm + 2*4224;        // [2][4224] payload (skewed)
    __shared__ unsigned wsumA[32], wsumB[32];
    __shared__ int vcount;
    __shared__ unsigned char slab[NBOX];
    __shared__ unsigned short cws[3][32];

    int f = blockIdx.x, tid = threadIdx.x, lane = tid & 31, wid = tid >> 5;
    const float* sc = scores + f*NBOX;
    if (tid == 0) vcount = 0;
    int vloc = 0;
    for (int i = tid; i < NBOX; i += 1024) {
        float s = sc[i];
        bool v = (s > SCORE_T);
        float skey = v ? s : -INFINITY;
        unsigned u = __float_as_uint(skey);
        u = (u & 0x80000000u) ? ~u : (u | 0x80000000u);
        kb[SKW(i)] = ~u;
        pb[SKW(i)] = (unsigned)i;
        vloc += v ? 1 : 0;
    }
    #pragma unroll
    for (int o = 16; o; o >>= 1) vloc += __shfl_xor_sync(0xffffffffu, vloc, o);
    if (lane == 0 && vloc) atomicAdd(&vcount, vloc);
    __syncthreads();

    int cur = 0;
    for (int pass = 0; pass < 16; ++pass) {
        int sh = pass * 2;
        unsigned* kc = kb + cur*4224;  unsigned* pc = pb + cur*4224;
        unsigned* kn = kb + (cur^1)*4224; unsigned* pn = pb + (cur^1)*4224;
        int b0 = tid*4;
        unsigned k0=kc[SKW(b0)],k1=kc[SKW(b0+1)],k2=kc[SKW(b0+2)],k3=kc[SKW(b0+3)];
        unsigned q0=pc[SKW(b0)],q1=pc[SKW(b0+1)],q2=pc[SKW(b0+2)],q3=pc[SKW(b0+3)];
        int d0=(k0>>sh)&3, d1=(k1>>sh)&3, d2=(k2>>sh)&3, d3=(k3>>sh)&3;
        unsigned cA=0, cB=0;
        #define ADDC(d) { if((d)==0) cA+=1u; else if((d)==1) cA+=(1u<<16); \
                          else if((d)==2) cB+=1u; else cB+=(1u<<16); }
        ADDC(d0) ADDC(d1) ADDC(d2) ADDC(d3)
        unsigned a=cA, b=cB;
        #pragma unroll
        for (int o=1;o<32;o<<=1){
            unsigned ta=__shfl_up_sync(0xffffffffu,a,o);
            unsigned tb=__shfl_up_sync(0xffffffffu,b,o);
            if(lane>=o){a+=ta;b+=tb;}
        }
        if (lane==31){ wsumA[wid]=a; wsumB[wid]=b; }
        __syncthreads();
        if (wid==0){
            unsigned x=wsumA[lane], y=wsumB[lane];
            #pragma unroll
            for(int o=1;o<32;o<<=1){
                unsigned tx=__shfl_up_sync(0xffffffffu,x,o);
                unsigned ty=__shfl_up_sync(0xffffffffu,y,o);
                if(lane>=o){x+=tx;y+=ty;}
            }
            wsumA[lane]=x; wsumB[lane]=y;
        }
        __syncthreads();
        unsigned wa = wid ? wsumA[wid-1] : 0u, wb = wid ? wsumB[wid-1] : 0u;
        unsigned exA = a - cA + wa, exB = b - cB + wb;
        unsigned totA = wsumA[31], totB = wsumB[31];
        unsigned T0 = totA & 0xffffu, T1 = totA >> 16, T2 = totB & 0xffffu;
        unsigned base1 = T0, base2 = T0+T1, base3 = base2+T2;
        unsigned off[4];
        off[0]=(exA&0xffffu); off[1]=base1+(exA>>16);
        off[2]=base2+(exB&0xffffu); off[3]=base3+(exB>>16);
        unsigned dd;
        dd=off[d0]++; kn[SKW(dd)]=k0; pn[SKW(dd)]=q0;
        dd=off[d1]++; kn[SKW(dd)]=k1; pn[SKW(dd)]=q1;
        dd=off[d2]++; kn[SKW(dd)]=k2; pn[SKW(dd)]=q2;
        dd=off[d3]++; kn[SKW(dd)]=k3; pn[SKW(dd)]=q3;
        __syncthreads();
        cur ^= 1;
    }
    int V = vcount;
    if (tid == 0) d_V[f] = V;
    int base = f*NBOX;

    unsigned* pf = pb + cur*4224;
    int r0 = tid*4;
    #pragma unroll
    for (int u = 0; u < 4; ++u) {
        int r = r0 + u;
        int o = (int)pf[SKW(r)];
        const float* bx = boxes + ((size_t)f*NBOX + o)*7;
        float b0 = bx[0], b1 = bx[1], b2 = bx[2], b3 = bx[3],
              b4 = bx[4], b5 = bx[5], b6 = bx[6];
        float s  = sc[o];
        int  lab = labels[f*NBOX + o];
        float off = (float)lab * 10000.0f;
        float cx = b0 + off, cy = b1;
        float hx = b3 * 0.5f, hy = b4 * 0.5f;
        float x1 = cx - hx, x2 = cx + hx, y1 = cy - hy, y2 = cy + hy;
        float area = (x2 - x1) * (y2 - y1);
        int idx = base + r;
        float* sb = d_sbox + (size_t)idx*7;
        sb[0]=b0; sb[1]=b1; sb[2]=b2; sb[3]=b3; sb[4]=b4; sb[5]=b5; sb[6]=b6;
        d_sscore[idx] = s; d_slabel[idx] = (float)lab;
        d_x1[idx]=x1; d_x2[idx]=x2; d_y1[idx]=y1; d_y2[idx]=y2; d_areaA[idx]=area;
        slab[r] = (unsigned char)lab;
    }
    __syncthreads();

    unsigned pk = 0;
    int lb[4];
    #pragma unroll
    for (int u = 0; u < 4; ++u) {
        int r = r0 + u;
        lb[u] = slab[r];
        if (r < V) pk += 1u << (lb[u]*10);
    }
    unsigned inc = pk;
    #pragma unroll
    for (int o=1;o<32;o<<=1){ unsigned t=__shfl_up_sync(0xffffffffu,inc,o); if(lane>=o) inc+=t; }
    unsigned ex = inc - pk;
    if (lane == 31) {
        cws[0][wid] = (unsigned short)( inc        & 1023u);
        cws[1][wid] = (unsigned short)((inc >> 10) & 1023u);
        cws[2][wid] = (unsigned short)((inc >> 20) & 1023u);
    }
    __syncthreads();
    if (tid < 32) {
        #pragma unroll
        for (int c2 = 0; c2 < 3; ++c2) {
            unsigned v = cws[c2][lane];
            #pragma unroll
            for (int o=1;o<32;o<<=1){ unsigned t=__shfl_up_sync(0xffffffffu,v,o); if(lane>=o) v+=t; }
            cws[c2][lane] = (unsigned short)v;
        }
    }
    __syncthreads();
    int offc[3];
    #pragma unroll
    for (int c2 = 0; c2 < 3; ++c2)
        offc[c2] = (wid ? (int)cws[c2][wid-1] : 0) + (int)((ex >> (10*c2)) & 1023u);
    #pragma unroll
    for (int u = 0; u < 4; ++u) {
        int r = r0 + u;
        if (r < V) {
            int c2 = lb[u];
            int p  = offc[c2]++;
            int idx = base + r;
            int ci  = (f*3 + c2)*NBOX + p;
            d_clsGeo [ci] = make_float4(d_x1[idx], d_x2[idx], d_y1[idx], d_y2[idx]);
            d_clsArea[ci] = d_areaA[idx];
            d_clsG   [ci] = r;
        }
    }
    if (tid < 3) d_Vc[f*3 + tid] = (int)cws[tid][31];
}

// ---------------- kernel 2: per-class neighbor lists, 2 boxes/thread --------
__global__ void __launch_bounds__(256) k_nbr()
{
    int f = blockIdx.z, c = blockIdx.y, chunk = blockIdx.x;
    int Vc = d_Vc[f*3 + c];
    int i0 = chunk * 512;
    if (i0 >= Vc) return;
    int tid = threadIdx.x;
    int iA = i0 + tid;
    int iB = i0 + 256 + tid;
    bool actA = iA < Vc, actB = iB < Vc;
    int cbase = (f*3 + c)*NBOX;
    int base  = f*NBOX;

    float4 gA = make_float4(0,0,0,0), gB = make_float4(0,0,0,0);
    float  aA = 0.f, aB = 0.f;
    int    gidxA = 0, gidxB = 0;
    if (actA) { gA = d_clsGeo[cbase+iA]; aA = d_clsArea[cbase+iA]; gidxA = d_clsG[cbase+iA]; }
    if (actB) { gB = d_clsGeo[cbase+iB]; aB = d_clsArea[cbase+iB]; gidxB = d_clsG[cbase+iB]; }

    __shared__ float4 sg[256];
    __shared__ float  sa[256];
    __shared__ int    sgi[256];

    int cntA = 0, spA = 0, cntB = 0, spB = 0;
    int* lstA = d_nbr + (size_t)(base + gidxA) * CAP;
    int* lstB = d_nbr + (size_t)(base + gidxB) * CAP;

    for (int j0 = 0; j0 < Vc; j0 += 256) {
        __syncthreads();
        int j = j0 + tid;
        if (j < Vc) { sg[tid] = d_clsGeo[cbase+j]; sa[tid] = d_clsArea[cbase+j]; sgi[tid] = d_clsG[cbase+j]; }
        __syncthreads();
        int lim = min(256, Vc - j0);
        #pragma unroll 2
        for (int jj = 0; jj < lim; ++jj) {
            float4 t = sg[jj];
            float aj = sa[jj];
            float ixA = fminf(gA.y, t.y) - fmaxf(gA.x, t.x);
            float iyA = fminf(gA.w, t.w) - fmaxf(gA.z, t.z);
            float ixB = fminf(gB.y, t.y) - fmaxf(gB.x, t.x);
            float iyB = fminf(gB.w, t.w) - fmaxf(gB.z, t.z);
            if (actA && ixA > 0.f && iyA > 0.f) {
                float inter = ixA * iyA;
                float den   = fmaxf(aA + aj - inter, 1e-6f);
                if (inter / den > IOU_T && cntA < CAP) {
                    int jg = sgi[jj];
                    if (jg == gidxA) spA = cntA;
                    lstA[cntA++] = jg;
                }
            }
            if (actB && ixB > 0.f && iyB > 0.f) {
                float inter = ixB * iyB;
                float den   = fmaxf(aB + aj - inter, 1e-6f);
                if (inter / den > IOU_T && cntB < CAP) {
                    int jg = sgi[jj];
                    if (jg == gidxB) spB = cntB;
                    lstB[cntB++] = jg;
                }
            }
        }
    }
    if (actA) { d_deg[base + gidxA] = cntA; d_selfpos[base + gidxA] = spA; }
    if (actB) { d_deg[base + gidxB] = cntB; d_selfpos[base + gidxB] = spB; }
}

// ---------------- kernel 3: parallel lex-first greedy, shared-cached --------
__global__ void __launch_bounds__(1024) k_scan()
{
    extern __shared__ char smc[];
    unsigned short* inl  = (unsigned short*)smc;                       // NBOX*INL
    unsigned short* spA  = (unsigned short*)(smc + NBOX*INL*2);        // NBOX
    unsigned short* cid  = spA + NBOX;                                 // NBOX
    unsigned char*  state= (unsigned char*)(cid + NBOX);               // NBOX
    __shared__ int changed;
    volatile unsigned char* vstate = state;

    int f = blockIdx.x, tid = threadIdx.x;
    int base = f*NBOX;
    int V = d_V[f];

    for (int i = tid; i < NBOX; i += 1024) {
        d_lead[base + i] = 0;
        state[i] = (i < V) ? (unsigned char)0 : (unsigned char)2;
    }
    for (int i = tid; i < V; i += 1024) {
        int sp = d_selfpos[base + i];
        spA[i] = (unsigned short)sp;
        const int* g = d_nbr + (size_t)(base + i) * CAP;
        int m = sp < INL ? sp : INL;
        for (int k = 0; k < m; ++k) inl[i*INL + k] = (unsigned short)g[k];
    }
    __syncthreads();

    for (int round = 0; round < 4096; ++round) {
        if (tid == 0) changed = 0;
        __syncthreads();
        for (int rep = 0; rep < 2; ++rep) {
            int i0 = tid * 4;
            #pragma unroll
            for (int u = 0; u < 4; ++u) {
                int i = i0 + u;
                if (vstate[i] != 0) continue;
                int sp = spA[i];
                bool any1 = false, any0 = false;
                int m = sp < INL ? sp : INL;
                for (int k = 0; k < m; ++k) {
                    unsigned char s = vstate[inl[i*INL + k]];
                    any1 |= (s == 1); any0 |= (s == 0);
                }
                if (sp > INL && !any1) {
                    const int* g = d_nbr + (size_t)(base + i) * CAP;
                    for (int k = INL; k < sp && !any1; ++k) {
                        unsigned char s = vstate[g[k]];
                        any1 |= (s == 1); any0 |= (s == 0);
                    }
                }
                if (any1)       { vstate[i] = 2; changed = 1; }
                else if (!any0) { vstate[i] = 1; changed = 1; }
            }
        }
        __syncthreads();
        if (!changed) break;
        __syncthreads();
    }

    for (int i = tid; i < V; i += 1024) {
        if (state[i] == 1) { cid[i] = (unsigned short)i; continue; }
        int sp = spA[i];
        int c = 0xFFFF;
        int m = sp < INL ? sp : INL;
        for (int k = 0; k < m; ++k) {
            int j = inl[i*INL + k];
            if (state[j] == 1) { c = j; break; }
        }
        if (c == 0xFFFF && sp > INL) {
            const int* g = d_nbr + (size_t)(base + i) * CAP;
            for (int k = INL; k < sp; ++k) {
                int j = g[k];
                if (state[j] == 1) { c = j; break; }
            }
        }
        cid[i] = (unsigned short)c;
    }
    __syncthreads();

    for (int i = tid; i < V; i += 1024) {
        if (state[i] != 1) continue;
        int* outl = d_clusIdx + (base + i)*MAXC;
        outl[0] = i;
        const int* lst = d_nbr + (size_t)(base + i) * CAP;
        int sp = spA[i], dg = d_deg[base + i];
        int r = 1;
        for (int k = sp + 1; k < dg; ++k) {
            int m = lst[k];
            if (cid[m] == (unsigned short)i) { if (r < MAXC) outl[r] = m; ++r; }
        }
        d_count[base + i] = (r < MAXC) ? r : MAXC;
        d_lead [base + i] = 1;
    }
}

// ---------------- kernel 4: MLP + softmax merge + output --------------------
__global__ void __launch_bounds__(256) k_merge(const float* __restrict__ W1,
                                               const float* __restrict__ b1,
                                               const float* __restrict__ W2,
                                               const float* __restrict__ b2,
                                               float* __restrict__ out, int writeLead)
{
    __shared__ float sW1[448], sb1[64], sW2[64];
    __shared__ float sb2;
    int tid = threadIdx.x;
    int g = tid >> 4, l = tid & 15;
    unsigned gm = 0xFFFFu << (tid & 16);
    int row = blockIdx.x * 16 + g;
    int lead = d_lead[row];
    int cnt  = lead ? d_count[row] : 0;

    int need = __syncthreads_or(cnt >= 2);
    if (need) {
        for (int t = tid; t < 448; t += 256) sW1[t] = W1[t];
        if (tid < 64) { sb1[tid] = b1[tid]; sW2[tid] = W2[tid]; }
        if (tid == 0) sb2 = b2[0];
        __syncthreads();
    }

    float* infoOut = out + (size_t)row * 9;
    if (!lead) {
        if (l == 0) {
            #pragma unroll
            for (int d = 0; d < 9; ++d) infoOut[d] = 0.f;
            if (writeLead) out[(size_t)NFRAME*NBOX*9 + row] = 0.f;
        }
        return;
    }
    if (cnt == 1) {
        if (l == 0) {
            const float* own = d_sbox + (size_t)row * 7;
            infoOut[0]=own[0]; infoOut[1]=own[1]; infoOut[2]=own[2];
            infoOut[3]=own[3]; infoOut[4]=own[4]; infoOut[5]=own[5];
            infoOut[6]=own[6];
            infoOut[7]=d_sscore[row];
            infoOut[8]=d_slabel[row];
            if (writeLead) out[(size_t)NFRAME*NBOX*9 + row] = 1.f;
        }
        return;
    }
    bool ok = l < cnt;
    float c[7];
    int f = row >> 12;
    if (ok) {
        int nb = d_clusIdx[row*MAXC + l];
        const float* sp = d_sbox + ((size_t)(f*NBOX) + nb) * 7;
        #pragma unroll
        for (int d = 0; d < 7; ++d) c[d] = sp[d];
    } else {
        #pragma unroll
        for (int d = 0; d < 7; ++d) c[d] = 0.f;
    }
    float logit;
    if (ok) {
        float lg = 0.f;
        for (int k = 0; k < 64; ++k) {
            float h = sb1[k];
            #pragma unroll
            for (int d = 0; d < 7; ++d) h += c[d] * sW1[d*64 + k];
            h = fmaxf(h, 0.f);
            lg += h * sW2[k];
        }
        logit = lg + sb2;
    } else logit = -1e9f;

    float m = logit;
    #pragma unroll
    for (int o = 8; o; o >>= 1) m = fmaxf(m, __shfl_xor_sync(gm, m, o, 16));
    float p = ok ? expf(logit - m) : 0.f;
    float S = p;
    #pragma unroll
    for (int o = 8; o; o >>= 1) S += __shfl_xor_sync(gm, S, o, 16);
    float w = p / S;
    float mg[7];
    #pragma unroll
    for (int d = 0; d < 7; ++d) {
        float v = w * c[d];
        #pragma unroll
        for (int o = 8; o; o >>= 1) v += __shfl_xor_sync(gm, v, o, 16);
        mg[d] = v;
    }
    if (l == 0) {
        const float* own = d_sbox + (size_t)row * 7;
        infoOut[0] = mg[0]; infoOut[1] = mg[1]; infoOut[2] = mg[2];
        infoOut[3] = (mg[3] <= 0.f) ? own[3] : mg[3];
        infoOut[4] = (mg[4] <= 0.f) ? own[4] : mg[4];
        infoOut[5] = (mg[5] <= 0.f) ? own[5] : mg[5];
        infoOut[6] = mg[6];
        infoOut[7] = d_sscore[row];
        infoOut[8] = d_slabel[row];
        if (writeLead) out[(size_t)NFRAME*NBOX*9 + row] = 1.f;
    }
}

// ---------------- launch -----------------------------------------------------
extern "C" void kernel_launch(void* const* d_in, const int* in_sizes, int n_in,
                              void* d_out, int out_size)
{
    const float* boxes  = (const float*)d_in[0];
    const float* scores = (const float*)d_in[1];
    const int*   labels = (const int*)  d_in[2];
    const float* W1     = (const float*)d_in[3];
    const float* b1     = (const float*)d_in[4];
    const float* W2     = (const float*)d_in[5];
    const float* b2     = (const float*)d_in[6];
    float* out = (float*)d_out;

    int writeLead = (out_size >= NFRAME*NBOX*10) ? 1 : 0;

    const int SMEM_SORT = 4*4224*4;                               // 67584
    const int SMEM_SCAN = NBOX*INL*2 + NBOX*2*2 + NBOX;           // 86016
    static int inited = 0;
    if (!inited) {
        cudaFuncSetAttribute(k_sort, cudaFuncAttributeMaxDynamicSharedMemorySize, SMEM_SORT);
        cudaFuncSetAttribute(k_scan, cudaFuncAttributeMaxDynamicSharedMemorySize, SMEM_SCAN);
        inited = 1;
    }

    k_sort<<<NFRAME, 1024, SMEM_SORT>>>(boxes, scores, labels);
    k_nbr<<<dim3(8, 3, NFRAME), 256>>>();
    k_scan<<<NFRAME, 1024, SMEM_SCAN>>>();
    k_merge<<<(NFRAME*NBOX)/16, 256>>>(W1, b1, W2, b2, out, writeLead);
}

// round 13
// speedup vs baseline: 2.2495x; 1.6518x over previous
#include <cuda_runtime.h>
#include <math.h>

#define NBOX   4096
#define NFRAME 4
#define CAPE   96
#define MAXC   16
#define INL    8
#define IOU_T   0.3f
#define SCORE_T 0.2f
#define SKW(i) ((i) + ((i) >> 5))
#define XLO    (-120.0f)
#define INVW   (256.0f/240.0f)

// ---------------- scratch (static __device__, no allocations) ----------------
__device__ float d_sbox  [NFRAME*NBOX*7];
__device__ float d_sscore[NFRAME*NBOX];
__device__ float d_slabel[NFRAME*NBOX];
__device__ int   d_V[NFRAME];
__device__ float4 d_clsGeo [NFRAME*NBOX];    // cell-ordered (x1,x2,y1,y2)
__device__ float  d_clsArea[NFRAME*NBOX];
__device__ int    d_clsG   [NFRAME*NBOX];    // gidx | (lab<<12)
__device__ int   d_cellStart[NFRAME*769];
__device__ int   d_in [NFRAME*NBOX*CAPE];
__device__ int   d_out[NFRAME*NBOX*CAPE];
__device__ int   d_indeg [NFRAME*NBOX];
__device__ int   d_outdeg[NFRAME*NBOX];
__device__ int   d_clusIdx[NFRAME*NBOX*MAXC];
__device__ int   d_count[NFRAME*NBOX];
__device__ int   d_lead[NFRAME*NBOX];

// ---------------- kernel 1: stable radix sort + gather + cell partition -----
__global__ void __launch_bounds__(1024) k_sort(const float* __restrict__ boxes,
                                               const float* __restrict__ scores,
                                               const int*   __restrict__ labels)
{
    extern __shared__ unsigned sm[];
    unsigned* kb = sm;                 // [2][4224] keys (skewed)
    unsigned* pb = sm + 2*4224;        // [2][4224] payload (skewed)
    __shared__ unsigned wsumA[32], wsumB[32];
    __shared__ unsigned hist[768], cursor[768], wps[24];
    __shared__ int vcount;

    int f = blockIdx.x, tid = threadIdx.x, lane = tid & 31, wid = tid >> 5;
    const float* sc = scores + f*NBOX;
    if (tid == 0) vcount = 0;
    if (tid < 768) hist[tid] = 0;
    int vloc = 0;
    for (int i = tid; i < NBOX; i += 1024) {
        float s = sc[i];
        bool v = (s > SCORE_T);
        float skey = v ? s : -INFINITY;
        unsigned u = __float_as_uint(skey);
        u = (u & 0x80000000u) ? ~u : (u | 0x80000000u);
        kb[SKW(i)] = ~u;
        pb[SKW(i)] = (unsigned)i;
        vloc += v ? 1 : 0;
    }
    #pragma unroll
    for (int o = 16; o; o >>= 1) vloc += __shfl_xor_sync(0xffffffffu, vloc, o);
    if (lane == 0 && vloc) atomicAdd(&vcount, vloc);
    __syncthreads();

    int cur = 0;
    for (int pass = 0; pass < 16; ++pass) {
        int sh = pass * 2;
        unsigned* kc = kb + cur*4224;  unsigned* pc = pb + cur*4224;
        unsigned* kn = kb + (cur^1)*4224; unsigned* pn = pb + (cur^1)*4224;
        int b0 = tid*4;
        unsigned k0=kc[SKW(b0)],k1=kc[SKW(b0+1)],k2=kc[SKW(b0+2)],k3=kc[SKW(b0+3)];
        unsigned q0=pc[SKW(b0)],q1=pc[SKW(b0+1)],q2=pc[SKW(b0+2)],q3=pc[SKW(b0+3)];
        int d0=(k0>>sh)&3, d1=(k1>>sh)&3, d2=(k2>>sh)&3, d3=(k3>>sh)&3;
        unsigned cA=0, cB=0;
        #define ADDC(d) { if((d)==0) cA+=1u; else if((d)==1) cA+=(1u<<16); \
                          else if((d)==2) cB+=1u; else cB+=(1u<<16); }
        ADDC(d0) ADDC(d1) ADDC(d2) ADDC(d3)
        unsigned a=cA, b=cB;
        #pragma unroll
        for (int o=1;o<32;o<<=1){
            unsigned ta=__shfl_up_sync(0xffffffffu,a,o);
            unsigned tb=__shfl_up_sync(0xffffffffu,b,o);
            if(lane>=o){a+=ta;b+=tb;}
        }
        if (lane==31){ wsumA[wid]=a; wsumB[wid]=b; }
        __syncthreads();
        if (wid==0){
            unsigned x=wsumA[lane], y=wsumB[lane];
            #pragma unroll
            for(int o=1;o<32;o<<=1){
                unsigned tx=__shfl_up_sync(0xffffffffu,x,o);
                unsigned ty=__shfl_up_sync(0xffffffffu,y,o);
                if(lane>=o){x+=tx;y+=ty;}
            }
            wsumA[lane]=x; wsumB[lane]=y;
        }
        __syncthreads();
        unsigned wa = wid ? wsumA[wid-1] : 0u, wb = wid ? wsumB[wid-1] : 0u;
        unsigned exA = a - cA + wa, exB = b - cB + wb;
        unsigned totA = wsumA[31], totB = wsumB[31];
        unsigned T0 = totA & 0xffffu, T1 = totA >> 16, T2 = totB & 0xffffu;
        unsigned bs1 = T0, bs2 = T0+T1, bs3 = bs2+T2;
        unsigned off[4];
        off[0]=(exA&0xffffu); off[1]=bs1+(exA>>16);
        off[2]=bs2+(exB&0xffffu); off[3]=bs3+(exB>>16);
        unsigned dd;
        dd=off[d0]++; kn[SKW(dd)]=k0; pn[SKW(dd)]=q0;
        dd=off[d1]++; kn[SKW(dd)]=k1; pn[SKW(dd)]=q1;
        dd=off[d2]++; kn[SKW(dd)]=k2; pn[SKW(dd)]=q2;
        dd=off[d3]++; kn[SKW(dd)]=k3; pn[SKW(dd)]=q3;
        __syncthreads();
        cur ^= 1;
    }
    int V = vcount;
    if (tid == 0) d_V[f] = V;
    int base = f*NBOX;

    // gather into sorted order; keep geometry in registers; cell histogram
    unsigned* pf = pb + cur*4224;
    int r0 = tid*4;
    float X1[4],X2[4],Y1[4],Y2[4],AR[4],XL1[4];
    int LB[4]; bool VA[4];
    #pragma unroll
    for (int u = 0; u < 4; ++u) {
        int r = r0 + u;
        int o = (int)pf[SKW(r)];
        const float* bx = boxes + ((size_t)f*NBOX + o)*7;
        float b0 = bx[0], b1 = bx[1], b2 = bx[2], b3 = bx[3],
              b4 = bx[4], b5 = bx[5], b6 = bx[6];
        float s  = sc[o];
        int  lab = labels[f*NBOX + o];
        float off = (float)lab * 10000.0f;
        float cx = b0 + off, cy = b1;
        float hx = b3 * 0.5f, hy = b4 * 0.5f;
        float x1 = cx - hx, x2 = cx + hx, y1 = cy - hy, y2 = cy + hy;
        float area = (x2 - x1) * (y2 - y1);
        int idx = base + r;
        float* sb = d_sbox + (size_t)idx*7;
        sb[0]=b0; sb[1]=b1; sb[2]=b2; sb[3]=b3; sb[4]=b4; sb[5]=b5; sb[6]=b6;
        d_sscore[idx] = s; d_slabel[idx] = (float)lab;
        X1[u]=x1; X2[u]=x2; Y1[u]=y1; Y2[u]=y2; AR[u]=area;
        XL1[u]=x1-off; LB[u]=lab; VA[u]=(r<V);
        if (VA[u]) {
            int cell = (int)((XL1[u] - XLO) * INVW);
            cell = cell < 0 ? 0 : (cell > 255 ? 255 : cell);
            atomicAdd(&hist[lab*256 + cell], 1u);
        }
    }
    __syncthreads();

    // exclusive prefix over 768 cells
    unsigned pv = 0, pincl = 0;
    if (tid < 768) {
        pv = hist[tid];
        unsigned x = pv;
        #pragma unroll
        for (int o=1;o<32;o<<=1){ unsigned t=__shfl_up_sync(0xffffffffu,x,o); if(lane>=o) x+=t; }
        if (lane == 31) wps[tid>>5] = x;
        pincl = x;
    }
    __syncthreads();
    if (tid == 0) {
        unsigned acc = 0;
        for (int k = 0; k < 24; ++k) { unsigned t = wps[k]; wps[k] = acc; acc += t; }
    }
    __syncthreads();
    if (tid < 768) {
        unsigned st = wps[tid>>5] + pincl - pv;
        cursor[tid] = st;
        d_cellStart[f*769 + tid] = (int)st;
    }
    if (tid == 0) d_cellStart[f*769 + 768] = V;
    __syncthreads();

    // scatter into cell order
    #pragma unroll
    for (int u = 0; u < 4; ++u) {
        if (VA[u]) {
            int cell = (int)((XL1[u] - XLO) * INVW);
            cell = cell < 0 ? 0 : (cell > 255 ? 255 : cell);
            unsigned pos = atomicAdd(&cursor[LB[u]*256 + cell], 1u);
            d_clsGeo [base + pos] = make_float4(X1[u], X2[u], Y1[u], Y2[u]);
            d_clsArea[base + pos] = AR[u];
            d_clsG   [base + pos] = (r0 + u) | (LB[u] << 12);
        }
    }
}

// ---------------- kernel 2: windowed in/out edge lists ----------------------
__global__ void __launch_bounds__(128) k_nbr()
{
    __shared__ int cs[769];
    int f = blockIdx.y;
    int V = d_V[f];
    int tid = threadIdx.x;
    for (int k = tid; k < 769; k += 128) cs[k] = d_cellStart[f*769 + k];
    __syncthreads();
    int il = blockIdx.x * 128 + tid;
    if (il >= V) return;
    int base = f*NBOX;

    float4 g  = d_clsGeo [base + il];
    float  ar = d_clsArea[base + il];
    int   info = d_clsG  [base + il];
    int r   = info & 4095;
    int lab = info >> 12;
    float off = (float)lab * 10000.0f;
    float xl1 = g.x - off, xl2 = g.y - off;
    int clo = (int)((xl1 - 4.6f - XLO) * INVW);
    int chi = (int)((xl2 + 0.1f - XLO) * INVW);
    clo = clo < 0 ? 0 : (clo > 255 ? 255 : clo);
    chi = chi < 0 ? 0 : (chi > 255 ? 255 : chi);

    int cin = 0, cout = 0;
    int* inl  = d_in  + (size_t)(base + r)*CAPE;
    int* outl = d_out + (size_t)(base + r)*CAPE;
    int hbase = lab*256;
    for (int cell = clo; cell <= chi; ++cell) {
        int s = cs[hbase + cell], e = cs[hbase + cell + 1];
        for (int k = s; k < e; ++k) {
            float4 t = d_clsGeo[base + k];
            float ix = fminf(g.y, t.y) - fmaxf(g.x, t.x);
            float iy = fminf(g.w, t.w) - fmaxf(g.z, t.z);
            if (ix > 0.f && iy > 0.f) {
                float inter = ix * iy;
                float den   = fmaxf(ar + d_clsArea[base + k] - inter, 1e-6f);
                if (inter / den > IOU_T) {
                    int jg = d_clsG[base + k] & 4095;
                    if (jg < r)      { if (cin  < CAPE) inl [cin++]  = jg; }
                    else if (jg > r) { if (cout < CAPE) outl[cout++] = jg; }
                }
            }
        }
    }
    d_indeg [base + r] = cin;
    d_outdeg[base + r] = cout;
}

// ---------------- kernel 3: parallel lex-first greedy via fixpoint ----------
__global__ void __launch_bounds__(1024) k_scan()
{
    extern __shared__ char smc[];
    unsigned short* inl  = (unsigned short*)smc;                       // NBOX*INL
    unsigned short* indA = (unsigned short*)(smc + NBOX*INL*2);        // NBOX
    unsigned short* cid  = indA + NBOX;                                // NBOX
    unsigned char*  state= (unsigned char*)(cid + NBOX);               // NBOX
    __shared__ int changed;
    volatile unsigned char* vstate = state;

    int f = blockIdx.x, tid = threadIdx.x;
    int base = f*NBOX;
    int V = d_V[f];

    for (int i = tid; i < NBOX; i += 1024) {
        d_lead[base + i] = 0;
        state[i] = (i < V) ? (unsigned char)0 : (unsigned char)2;
    }
    for (int i = tid; i < V; i += 1024) {
        int nd = d_indeg[base + i];
        indA[i] = (unsigned short)nd;
        const int* g = d_in + (size_t)(base + i) * CAPE;
        int m = nd < INL ? nd : INL;
        for (int k = 0; k < m; ++k) inl[i*INL + k] = (unsigned short)g[k];
    }
    __syncthreads();

    for (int round = 0; round < 4096; ++round) {
        if (tid == 0) changed = 0;
        __syncthreads();
        for (int rep = 0; rep < 2; ++rep) {
            int i0 = tid * 4;
            #pragma unroll
            for (int u = 0; u < 4; ++u) {
                int i = i0 + u;
                if (vstate[i] != 0) continue;
                int nd = indA[i];
                bool any1 = false, any0 = false;
                int m = nd < INL ? nd : INL;
                for (int k = 0; k < m; ++k) {
                    unsigned char s = vstate[inl[i*INL + k]];
                    any1 |= (s == 1); any0 |= (s == 0);
                }
                if (nd > INL && !any1) {
                    const int* g = d_in + (size_t)(base + i) * CAPE;
                    for (int k = INL; k < nd && !any1; ++k) {
                        unsigned char s = vstate[g[k]];
                        any1 |= (s == 1); any0 |= (s == 0);
                    }
                }
                if (any1)       { vstate[i] = 2; changed = 1; }
                else if (!any0) { vstate[i] = 1; changed = 1; }
            }
        }
        __syncthreads();
        if (!changed) break;
        __syncthreads();
    }

    // cluster ids: min leader among (unordered) in-neighbors
    for (int i = tid; i < V; i += 1024) {
        if (state[i] == 1) { cid[i] = (unsigned short)i; continue; }
        int nd = indA[i];
        int c = 0xFFFF;
        int m = nd < INL ? nd : INL;
        for (int k = 0; k < m; ++k) {
            int j = inl[i*INL + k];
            if (state[j] == 1 && j < c) c = j;
        }
        if (nd > INL) {
            const int* g = d_in + (size_t)(base + i) * CAPE;
            for (int k = INL; k < nd; ++k) {
                int j = g[k];
                if (state[j] == 1 && j < c) c = j;
            }
        }
        cid[i] = (unsigned short)c;
    }
    __syncthreads();

    // leaders: collect members (out-neighbors with cid==i), smallest-15 exact,
    // then ascending order (matches reference ranks bit-for-bit)
    for (int i = tid; i < V; i += 1024) {
        if (state[i] != 1) continue;
        int od = d_outdeg[base + i];
        const int* gout = d_out + (size_t)(base + i) * CAPE;
        int* outp = d_clusIdx + (base + i)*MAXC;
        outp[0] = i;
        int rc = 1;
        for (int k = 0; k < od; ++k) {
            int m = gout[k];
            if (cid[m] == (unsigned short)i) {
                if (rc < MAXC) outp[rc++] = m;
                else {
                    int mx = -1, mpos = -1;
                    for (int q = 1; q < MAXC; ++q)
                        if (outp[q] > mx) { mx = outp[q]; mpos = q; }
                    if (m < mx) outp[mpos] = m;
                }
            }
        }
        // insertion sort slots 1..rc-1 ascending
        for (int a = 2; a < rc; ++a) {
            int v = outp[a], b = a - 1;
            while (b >= 1 && outp[b] > v) { outp[b+1] = outp[b]; --b; }
            outp[b+1] = v;
        }
        d_count[base + i] = rc;
        d_lead [base + i] = 1;
    }
}

// ---------------- kernel 4: MLP + softmax merge + output --------------------
__global__ void __launch_bounds__(256) k_merge(const float* __restrict__ W1,
                                               const float* __restrict__ b1,
                                               const float* __restrict__ W2,
                                               const float* __restrict__ b2,
                                               float* __restrict__ out, int writeLead)
{
    __shared__ float sW1[448], sb1[64], sW2[64];
    __shared__ float sb2;
    int tid = threadIdx.x;
    int g = tid >> 4, l = tid & 15;
    unsigned gm = 0xFFFFu << (tid & 16);
    int row = blockIdx.x * 16 + g;
    int lead = d_lead[row];
    int cnt  = lead ? d_count[row] : 0;

    int need = __syncthreads_or(cnt >= 2);
    if (need) {
        for (int t = tid; t < 448; t += 256) sW1[t] = W1[t];
        if (tid < 64) { sb1[tid] = b1[tid]; sW2[tid] = W2[tid]; }
        if (tid == 0) sb2 = b2[0];
        __syncthreads();
    }

    float* infoOut = out + (size_t)row * 9;
    if (!lead) {
        if (l == 0) {
            #pragma unroll
            for (int d = 0; d < 9; ++d) infoOut[d] = 0.f;
            if (writeLead) out[(size_t)NFRAME*NBOX*9 + row] = 0.f;
        }
        return;
    }
    if (cnt == 1) {
        if (l == 0) {
            const float* own = d_sbox + (size_t)row * 7;
            infoOut[0]=own[0]; infoOut[1]=own[1]; infoOut[2]=own[2];
            infoOut[3]=own[3]; infoOut[4]=own[4]; infoOut[5]=own[5];
            infoOut[6]=own[6];
            infoOut[7]=d_sscore[row];
            infoOut[8]=d_slabel[row];
            if (writeLead) out[(size_t)NFRAME*NBOX*9 + row] = 1.f;
        }
        return;
    }
    bool ok = l < cnt;
    float c[7];
    int f = row >> 12;
    if (ok) {
        int nb = d_clusIdx[row*MAXC + l];
        const float* sp = d_sbox + ((size_t)(f*NBOX) + nb) * 7;
        #pragma unroll
        for (int d = 0; d < 7; ++d) c[d] = sp[d];
    } else {
        #pragma unroll
        for (int d = 0; d < 7; ++d) c[d] = 0.f;
    }
    float logit;
    if (ok) {
        float lg = 0.f;
        for (int k = 0; k < 64; ++k) {
            float h = sb1[k];
            #pragma unroll
            for (int d = 0; d < 7; ++d) h += c[d] * sW1[d*64 + k];
            h = fmaxf(h, 0.f);
            lg += h * sW2[k];
        }
        logit = lg + sb2;
    } else logit = -1e9f;

    float m = logit;
    #pragma unroll
    for (int o = 8; o; o >>= 1) m = fmaxf(m, __shfl_xor_sync(gm, m, o, 16));
    float p = ok ? expf(logit - m) : 0.f;
    float S = p;
    #pragma unroll
    for (int o = 8; o; o >>= 1) S += __shfl_xor_sync(gm, S, o, 16);
    float w = p / S;
    float mg[7];
    #pragma unroll
    for (int d = 0; d < 7; ++d) {
        float v = w * c[d];
        #pragma unroll
        for (int o = 8; o; o >>= 1) v += __shfl_xor_sync(gm, v, o, 16);
        mg[d] = v;
    }
    if (l == 0) {
        const float* own = d_sbox + (size_t)row * 7;
        infoOut[0] = mg[0]; infoOut[1] = mg[1]; infoOut[2] = mg[2];
        infoOut[3] = (mg[3] <= 0.f) ? own[3] : mg[3];
        infoOut[4] = (mg[4] <= 0.f) ? own[4] : mg[4];
        infoOut[5] = (mg[5] <= 0.f) ? own[5] : mg[5];
        infoOut[6] = mg[6];
        infoOut[7] = d_sscore[row];
        infoOut[8] = d_slabel[row];
        if (writeLead) out[(size_t)NFRAME*NBOX*9 + row] = 1.f;
    }
}

// ---------------- launch -----------------------------------------------------
extern "C" void kernel_launch(void* const* d_in_, const int* in_sizes, int n_in,
                              void* d_out_, int out_size)
{
    const float* boxes  = (const float*)d_in_[0];
    const float* scores = (const float*)d_in_[1];
    const int*   labels = (const int*)  d_in_[2];
    const float* W1     = (const float*)d_in_[3];
    const float* b1     = (const float*)d_in_[4];
    const float* W2     = (const float*)d_in_[5];
    const float* b2     = (const float*)d_in_[6];
    float* out = (float*)d_out_;

    int writeLead = (out_size >= NFRAME*NBOX*10) ? 1 : 0;

    const int SMEM_SORT = 4*4224*4;                               // 67584
    const int SMEM_SCAN = NBOX*INL*2 + NBOX*2*2 + NBOX;           // 86016
    static int inited = 0;
    if (!inited) {
        cudaFuncSetAttribute(k_sort, cudaFuncAttributeMaxDynamicSharedMemorySize, SMEM_SORT);
        cudaFuncSetAttribute(k_scan, cudaFuncAttributeMaxDynamicSharedMemorySize, SMEM_SCAN);
        inited = 1;
    }

    k_sort<<<NFRAME, 1024, SMEM_SORT>>>(boxes, scores, labels);
    k_nbr<<<dim3(32, NFRAME), 128>>>();
    k_scan<<<NFRAME, 1024, SMEM_SCAN>>>();
    k_merge<<<(NFRAME*NBOX)/16, 256>>>(W1, b1, W2, b2, out, writeLead);
}